// round 3
// baseline (speedup 1.0000x reference)
#include <cuda_runtime.h>

#define NJ 24
#define TB 16
#define NSLOT 68
#define SSTR (NJ * NSLOT)          // 1632 floats per sample slot
#define NTHREADS 384
#define SMEM_BYTES (2 * TB * SSTR * 4)   // 208896 B

// Kinematic-tree adjacency (self + parent + children), CSR. 70 nonzeros.
__constant__ int cPTR[NJ + 1] = {0,4,7,10,13,16,19,22,25,28,33,35,37,40,43,46,48,51,54,57,60,63,66,68,70};
__constant__ int cCOL[70] = {
    0,1,2,3,
    1,0,4,
    2,0,5,
    3,0,6,
    4,1,7,
    5,2,8,
    6,3,9,
    7,4,10,
    8,5,11,
    9,6,12,13,14,
    10,7,
    11,8,
    12,9,15,
    13,9,16,
    14,9,17,
    15,12,
    16,13,18,
    17,14,19,
    18,16,20,
    19,17,21,
    20,18,22,
    21,19,23,
    22,20,
    23,21};

// w3 repacked [24][64][68] (cols 65..67 zero) so rows are 16B-aligned for float4 loads.
__device__ float g_w3p[NJ * 64 * 68];

__global__ void prep_w3_kernel(const float* __restrict__ w3) {
    int idx = blockIdx.x * blockDim.x + threadIdx.x;
    if (idx < NJ * 64 * 68) {
        int j = idx % 68;
        int nl = idx / 68;
        g_w3p[idx] = (j < 65) ? w3[nl * 65 + j] : 0.0f;
    }
}

// Per-node linear: B[s][n][j] = sum_l A[s][n][l] * W[n][l][j]
// Thread owns (n, jv) = one joint x 4 output cols, accumulates all 16 samples.
template <int DIN, int DOUT>
__device__ __forceinline__ void linear_phase(const float* __restrict__ W,
                                             const float* __restrict__ A,
                                             float* __restrict__ Bf, int tid) {
    constexpr int JV = DOUT / 4;
    for (int t = tid; t < NJ * JV; t += NTHREADS) {
        int n = t / JV;
        int jv = t - n * JV;
        const float* wp = W + (n * DIN) * DOUT + jv * 4;
        const float* ap = A + n * NSLOT;
        float acc[TB][4];
#pragma unroll
        for (int s = 0; s < TB; s++) {
            acc[s][0] = 0.f; acc[s][1] = 0.f; acc[s][2] = 0.f; acc[s][3] = 0.f;
        }
#pragma unroll 4
        for (int l = 0; l < DIN; l++) {
            float4 wv = *reinterpret_cast<const float4*>(wp + l * DOUT);
#pragma unroll
            for (int s = 0; s < TB; s++) {
                float a = ap[s * SSTR + l];   // warp-broadcast LDS
                acc[s][0] = fmaf(a, wv.x, acc[s][0]);
                acc[s][1] = fmaf(a, wv.y, acc[s][1]);
                acc[s][2] = fmaf(a, wv.z, acc[s][2]);
                acc[s][3] = fmaf(a, wv.w, acc[s][3]);
            }
        }
        float* op = Bf + n * NSLOT + jv * 4;
#pragma unroll
        for (int s = 0; s < TB; s++)
            *reinterpret_cast<float4*>(op + s * SSTR) =
                make_float4(acc[s][0], acc[s][1], acc[s][2], acc[s][3]);
    }
}

// Sparse adjacency + bias (+ relu): A[s][n][j] = relu(sum_{m in N(n)} aw[n][m]*B[s][m][j] + bias[j])
__device__ __forceinline__ void adj_phase(const float* __restrict__ aw,
                                          const float* __restrict__ bias,
                                          const float* __restrict__ Bf,
                                          float* __restrict__ Aout,
                                          int tid, bool relu) {
    for (int t = tid; t < NJ * 16; t += NTHREADS) {
        int n = t >> 4;
        int jv = t & 15;
        float4 bb = *reinterpret_cast<const float4*>(bias + jv * 4);
        float acc[TB][4];
#pragma unroll
        for (int s = 0; s < TB; s++) {
            acc[s][0] = 0.f; acc[s][1] = 0.f; acc[s][2] = 0.f; acc[s][3] = 0.f;
        }
        int e1 = cPTR[n + 1];
        for (int e = cPTR[n]; e < e1; e++) {
            int m = cCOL[e];
            float v = aw[n * NJ + m];
            const float* bp = Bf + m * NSLOT + jv * 4;
#pragma unroll
            for (int s = 0; s < TB; s++) {
                float4 hv = *reinterpret_cast<const float4*>(bp + s * SSTR);
                acc[s][0] = fmaf(v, hv.x, acc[s][0]);
                acc[s][1] = fmaf(v, hv.y, acc[s][1]);
                acc[s][2] = fmaf(v, hv.z, acc[s][2]);
                acc[s][3] = fmaf(v, hv.w, acc[s][3]);
            }
        }
        float* op = Aout + n * NSLOT + jv * 4;
#pragma unroll
        for (int s = 0; s < TB; s++) {
            float r0 = acc[s][0] + bb.x;
            float r1 = acc[s][1] + bb.y;
            float r2 = acc[s][2] + bb.z;
            float r3 = acc[s][3] + bb.w;
            if (relu) {
                r0 = fmaxf(r0, 0.f); r1 = fmaxf(r1, 0.f);
                r2 = fmaxf(r2, 0.f); r3 = fmaxf(r3, 0.f);
            }
            *reinterpret_cast<float4*>(op + s * SSTR) = make_float4(r0, r1, r2, r3);
        }
    }
}

// Final adjacency + bias, write straight to gmem (dout=65, scalar j for coalescing).
__device__ __forceinline__ void adj_final(const float* __restrict__ aw,
                                          const float* __restrict__ bias,
                                          const float* __restrict__ Bf,
                                          float* __restrict__ outp,
                                          int nvalid, int tid) {
    for (int t = tid; t < NJ * 65; t += NTHREADS) {
        int n = t / 65;
        int j = t - n * 65;
        float bb = bias[j];
        float acc[TB];
#pragma unroll
        for (int s = 0; s < TB; s++) acc[s] = bb;
        int e1 = cPTR[n + 1];
        for (int e = cPTR[n]; e < e1; e++) {
            int m = cCOL[e];
            float v = aw[n * NJ + m];
            const float* bp = Bf + m * NSLOT + j;
#pragma unroll
            for (int s = 0; s < TB; s++)
                acc[s] = fmaf(v, bp[s * SSTR], acc[s]);
        }
#pragma unroll
        for (int s = 0; s < TB; s++)
            if (s < nvalid) outp[(size_t)s * (NJ * 65) + n * 65 + j] = acc[s];
    }
}

__global__ __launch_bounds__(NTHREADS, 1)
void gnn_fused(const float* __restrict__ x,
               const float* __restrict__ w0, const float* __restrict__ w1,
               const float* __restrict__ w2,
               const float* __restrict__ aw0, const float* __restrict__ aw1,
               const float* __restrict__ aw2, const float* __restrict__ aw3,
               const float* __restrict__ b0, const float* __restrict__ b1,
               const float* __restrict__ b2, const float* __restrict__ b3,
               float* __restrict__ out, int Btot) {
    extern __shared__ float smem[];
    float* Abuf = smem;
    float* Bbuf = smem + TB * SSTR;
    int tid = threadIdx.x;
    int B0 = blockIdx.x * TB;
    int nvalid = Btot - B0;
    if (nvalid > TB) nvalid = TB;

    // Load x tile (contiguous 16*24*13 floats), apply root mask (joint 0 -> 0).
    for (int i = tid; i < TB * NJ * 13; i += NTHREADS) {
        int s = i / (NJ * 13);
        int r = i - s * (NJ * 13);
        int n = r / 13;
        int c = r - n * 13;
        float v = 0.0f;
        if (s < nvalid && n != 0) v = x[(size_t)B0 * (NJ * 13) + i];
        Abuf[s * SSTR + n * NSLOT + c] = v;
    }
    __syncthreads();

    linear_phase<13, 64>(w0, Abuf, Bbuf, tid);  __syncthreads();
    adj_phase(aw0, b0, Bbuf, Abuf, tid, true);  __syncthreads();
    linear_phase<64, 64>(w1, Abuf, Bbuf, tid);  __syncthreads();
    adj_phase(aw1, b1, Bbuf, Abuf, tid, true);  __syncthreads();
    linear_phase<64, 64>(w2, Abuf, Bbuf, tid);  __syncthreads();
    adj_phase(aw2, b2, Bbuf, Abuf, tid, true);  __syncthreads();
    linear_phase<64, 68>(g_w3p, Abuf, Bbuf, tid); __syncthreads();
    adj_final(aw3, b3, Bbuf, out + (size_t)B0 * (NJ * 65), nvalid, tid);
}

extern "C" void kernel_launch(void* const* d_in, const int* in_sizes, int n_in,
                              void* d_out, int out_size) {
    // Identify inputs by element count (robust to metadata ordering).
    const float* x = nullptr;
    const float* w[4] = {nullptr, nullptr, nullptr, nullptr};
    const float* aw[4] = {nullptr, nullptr, nullptr, nullptr};
    const float* b[4] = {nullptr, nullptr, nullptr, nullptr};
    int iw12 = 1, iaw = 0, ib = 0;
    int Btot = 0;
    for (int i = 0; i < n_in; i++) {
        int sz = in_sizes[i];
        const float* p = (const float*)d_in[i];
        if (sz == 24 * 13 * 64) {
            w[0] = p;
        } else if (sz == 24 * 64 * 64) {
            if (iw12 < 3) w[iw12++] = p;
        } else if (sz == 24 * 64 * 65) {
            w[3] = p;
        } else if (sz == 24 * 24) {
            if (iaw < 4) aw[iaw++] = p;
        } else if (sz == 64) {
            if (ib < 3) b[ib++] = p;
        } else if (sz == 65) {
            b[3] = p;
        } else {
            x = p;
            Btot = sz / (NJ * 13);
        }
    }

    (void)cudaFuncSetAttribute(gnn_fused, cudaFuncAttributeMaxDynamicSharedMemorySize, SMEM_BYTES);

    prep_w3_kernel<<<(NJ * 64 * 68 + 255) / 256, 256>>>(w[3]);

    int blocks = (Btot + TB - 1) / TB;
    gnn_fused<<<blocks, NTHREADS, SMEM_BYTES>>>(
        x, w[0], w[1], w[2],
        aw[0], aw[1], aw[2], aw[3],
        b[0], b[1], b[2], b[3],
        (float*)d_out, Btot);
}

// round 4
// speedup vs baseline: 1.0463x; 1.0463x over previous
#include <cuda_runtime.h>

#define NJ 24
#define TB 16
#define NP 8                       // sample pairs per block (f32x2 packing)
#define NSLOT 68
#define PSTR (NJ * NSLOT)          // float2 elements per pair-slot stride
#define NTHREADS 384
#define SMEM_BYTES (2 * NP * PSTR * 8)   // 208896 B (two float2 buffers)

typedef unsigned long long ull;

// ---- f32x2 packed helpers (ptxas never emits FFMA2 from C++) ----
__device__ __forceinline__ ull pack2(float lo, float hi) {
    ull r; asm("mov.b64 %0, {%1, %2};" : "=l"(r) : "f"(lo), "f"(hi)); return r;
}
__device__ __forceinline__ ull fma2(ull a, ull b, ull c) {
    ull d; asm("fma.rn.f32x2 %0, %1, %2, %3;" : "=l"(d) : "l"(a), "l"(b), "l"(c)); return d;
}
__device__ __forceinline__ ull add2(ull a, ull b) {
    ull d; asm("add.rn.f32x2 %0, %1, %2;" : "=l"(d) : "l"(a), "l"(b)); return d;
}
__device__ __forceinline__ ull relu2(ull v) {
    float lo, hi;
    asm("mov.b64 {%0, %1}, %2;" : "=f"(lo), "=f"(hi) : "l"(v));
    return pack2(fmaxf(lo, 0.f), fmaxf(hi, 0.f));
}

// Kinematic-tree adjacency (self + parent + children), CSR. 70 nonzeros.
__constant__ int cPTR[NJ + 1] = {0,4,7,10,13,16,19,22,25,28,33,35,37,40,43,46,48,51,54,57,60,63,66,68,70};
__constant__ int cCOL[70] = {
    0,1,2,3,  1,0,4,  2,0,5,  3,0,6,  4,1,7,  5,2,8,  6,3,9,  7,4,10,
    8,5,11,  9,6,12,13,14,  10,7,  11,8,  12,9,15,  13,9,16,  14,9,17,
    15,12,  16,13,18,  17,14,19,  18,16,20,  19,17,21,  20,18,22,
    21,19,23,  22,20,  23,21};

// w3 repacked [24][64][68] (cols 65..67 zero) so rows are 16B-aligned for float4 loads.
__device__ float g_w3p[NJ * 64 * 68];

__global__ void prep_w3_kernel(const float* __restrict__ w3) {
    int idx = blockIdx.x * blockDim.x + threadIdx.x;
    if (idx < NJ * 64 * 68) {
        int j = idx % 68;
        int nl = idx / 68;
        g_w3p[idx] = (j < 65) ? w3[nl * 65 + j] : 0.0f;
    }
}

// Per-node linear on pair-packed activations.
// A, Bf are float2 buffers: element (p, n, c) at [(p*NJ + n)*NSLOT + c].
// Thread owns (n, jv) = one joint x 4 output cols, accumulates all 8 pairs via FFMA2.
template <int DIN, int DOUT>
__device__ __forceinline__ void linear_phase(const float* __restrict__ W,
                                             const float2* __restrict__ A,
                                             float2* __restrict__ Bf, int tid) {
    constexpr int JV = DOUT / 4;
    for (int t = tid; t < NJ * JV; t += NTHREADS) {
        int n = t / JV;
        int jv = t - n * JV;
        const float* wp = W + (n * DIN) * DOUT + jv * 4;
        const float2* ap = A + n * NSLOT;
        ull acc[NP][4];
#pragma unroll
        for (int p = 0; p < NP; p++) {
            acc[p][0] = 0ull; acc[p][1] = 0ull; acc[p][2] = 0ull; acc[p][3] = 0ull;
        }
#pragma unroll 4
        for (int l = 0; l < DIN; l++) {
            float4 wv = *reinterpret_cast<const float4*>(wp + l * DOUT);
            ull wx = pack2(wv.x, wv.x), wy = pack2(wv.y, wv.y);
            ull wz = pack2(wv.z, wv.z), ww = pack2(wv.w, wv.w);
#pragma unroll
            for (int p = 0; p < NP; p++) {
                ull a2 = *reinterpret_cast<const ull*>(ap + p * PSTR + l);  // LDS.64 broadcast
                acc[p][0] = fma2(a2, wx, acc[p][0]);
                acc[p][1] = fma2(a2, wy, acc[p][1]);
                acc[p][2] = fma2(a2, wz, acc[p][2]);
                acc[p][3] = fma2(a2, wz = wz, acc[p][2]), acc[p][2] = acc[p][2]; // placeholder removed below
            }
        }
    }
}

// NOTE: the template above is replaced by the corrected version below; kept out of use.

template <int DIN, int DOUT>
__device__ __forceinline__ void linear2(const float* __restrict__ W,
                                        const float2* __restrict__ A,
                                        float2* __restrict__ Bf, int tid) {
    constexpr int JV = DOUT / 4;
    for (int t = tid; t < NJ * JV; t += NTHREADS) {
        int n = t / JV;
        int jv = t - n * JV;
        const float* wp = W + (n * DIN) * DOUT + jv * 4;
        const float2* ap = A + n * NSLOT;
        ull acc[NP][4];
#pragma unroll
        for (int p = 0; p < NP; p++) {
            acc[p][0] = 0ull; acc[p][1] = 0ull; acc[p][2] = 0ull; acc[p][3] = 0ull;
        }
#pragma unroll 4
        for (int l = 0; l < DIN; l++) {
            float4 wv = *reinterpret_cast<const float4*>(wp + l * DOUT);
            ull wx = pack2(wv.x, wv.x), wy = pack2(wv.y, wv.y);
            ull wz = pack2(wv.z, wv.z), ww = pack2(wv.w, wv.w);
#pragma unroll
            for (int p = 0; p < NP; p++) {
                ull a2 = *reinterpret_cast<const ull*>(ap + p * PSTR + l);  // LDS.64 broadcast
                acc[p][0] = fma2(a2, wx, acc[p][0]);
                acc[p][1] = fma2(a2, wy, acc[p][1]);
                acc[p][2] = fma2(a2, wz, acc[p][2]);
                acc[p][3] = fma2(a2, ww, acc[p][3]);
            }
        }
        float2* op = Bf + n * NSLOT + jv * 4;
#pragma unroll
        for (int p = 0; p < NP; p++) {
            ulonglong2 v0; v0.x = acc[p][0]; v0.y = acc[p][1];
            ulonglong2 v1; v1.x = acc[p][2]; v1.y = acc[p][3];
            *reinterpret_cast<ulonglong2*>(op + p * PSTR)     = v0;  // STS.128
            *reinterpret_cast<ulonglong2*>(op + p * PSTR + 2) = v1;
        }
    }
}

// Sparse adjacency + bias (+relu) on pair-packed data.
__device__ __forceinline__ void adj2(const float* __restrict__ aw,
                                     const float* __restrict__ bias,
                                     const float2* __restrict__ Bf,
                                     float2* __restrict__ Aout,
                                     int tid, bool relu) {
    for (int t = tid; t < NJ * 16; t += NTHREADS) {
        int n = t >> 4;
        int jv = t & 15;
        float4 bbv = *reinterpret_cast<const float4*>(bias + jv * 4);
        ull acc[NP][4];
#pragma unroll
        for (int p = 0; p < NP; p++) {
            acc[p][0] = 0ull; acc[p][1] = 0ull; acc[p][2] = 0ull; acc[p][3] = 0ull;
        }
        int e1 = cPTR[n + 1];
        for (int e = cPTR[n]; e < e1; e++) {
            int m = cCOL[e];
            float v = aw[n * NJ + m];
            ull v2 = pack2(v, v);
            const float2* bp = Bf + m * NSLOT + jv * 4;
#pragma unroll
            for (int p = 0; p < NP; p++) {
                ulonglong2 h0 = *reinterpret_cast<const ulonglong2*>(bp + p * PSTR);      // LDS.128
                ulonglong2 h1 = *reinterpret_cast<const ulonglong2*>(bp + p * PSTR + 2);
                acc[p][0] = fma2(v2, h0.x, acc[p][0]);
                acc[p][1] = fma2(v2, h0.y, acc[p][1]);
                acc[p][2] = fma2(v2, h1.x, acc[p][2]);
                acc[p][3] = fma2(v2, h1.y, acc[p][3]);
            }
        }
        ull bb0 = pack2(bbv.x, bbv.x), bb1 = pack2(bbv.y, bbv.y);
        ull bb2 = pack2(bbv.z, bbv.z), bb3 = pack2(bbv.w, bbv.w);
        float2* op = Aout + n * NSLOT + jv * 4;
#pragma unroll
        for (int p = 0; p < NP; p++) {
            ull r0 = add2(acc[p][0], bb0);
            ull r1 = add2(acc[p][1], bb1);
            ull r2 = add2(acc[p][2], bb2);
            ull r3 = add2(acc[p][3], bb3);
            if (relu) { r0 = relu2(r0); r1 = relu2(r1); r2 = relu2(r2); r3 = relu2(r3); }
            ulonglong2 v0; v0.x = r0; v0.y = r1;
            ulonglong2 v1; v1.x = r2; v1.y = r3;
            *reinterpret_cast<ulonglong2*>(op + p * PSTR)     = v0;
            *reinterpret_cast<ulonglong2*>(op + p * PSTR + 2) = v1;
        }
    }
}

// Final adjacency + bias, unpack pairs and write straight to gmem (dout=65).
__device__ __forceinline__ void adj_final2(const float* __restrict__ aw,
                                           const float* __restrict__ bias,
                                           const float2* __restrict__ Bf,
                                           float* __restrict__ outp,
                                           int nvalid, int tid) {
    for (int t = tid; t < NJ * 65; t += NTHREADS) {
        int n = t / 65;
        int j = t - n * 65;
        float bb = bias[j];
        float ax[NP], ay[NP];
#pragma unroll
        for (int p = 0; p < NP; p++) { ax[p] = bb; ay[p] = bb; }
        int e1 = cPTR[n + 1];
        for (int e = cPTR[n]; e < e1; e++) {
            int m = cCOL[e];
            float v = aw[n * NJ + m];
            const float2* bp = Bf + m * NSLOT + j;
#pragma unroll
            for (int p = 0; p < NP; p++) {
                float2 h = bp[p * PSTR];
                ax[p] = fmaf(v, h.x, ax[p]);
                ay[p] = fmaf(v, h.y, ay[p]);
            }
        }
#pragma unroll
        for (int p = 0; p < NP; p++) {
            int s0 = 2 * p, s1 = 2 * p + 1;
            if (s0 < nvalid) outp[(size_t)s0 * (NJ * 65) + n * 65 + j] = ax[p];
            if (s1 < nvalid) outp[(size_t)s1 * (NJ * 65) + n * 65 + j] = ay[p];
        }
    }
}

__global__ __launch_bounds__(NTHREADS, 1)
void gnn_fused(const float* __restrict__ x,
               const float* __restrict__ w0, const float* __restrict__ w1,
               const float* __restrict__ w2,
               const float* __restrict__ aw0, const float* __restrict__ aw1,
               const float* __restrict__ aw2, const float* __restrict__ aw3,
               const float* __restrict__ b0, const float* __restrict__ b1,
               const float* __restrict__ b2, const float* __restrict__ b3,
               float* __restrict__ out, int Btot) {
    extern __shared__ float2 smem[];
    float2* Abuf = smem;
    float2* Bbuf = smem + NP * PSTR;
    int tid = threadIdx.x;
    int B0 = blockIdx.x * TB;
    int nvalid = Btot - B0;
    if (nvalid > TB) nvalid = TB;

    // Load x tile into pair-interleaved layout, apply root mask (joint 0 -> 0).
    for (int i = tid; i < TB * NJ * 13; i += NTHREADS) {
        int s = i / (NJ * 13);
        int r = i - s * (NJ * 13);
        int n = r / 13;
        int c = r - n * 13;
        float v = 0.0f;
        if (s < nvalid && n != 0) v = x[(size_t)B0 * (NJ * 13) + i];
        float* dst = reinterpret_cast<float*>(Abuf);
        dst[(((s >> 1) * NJ + n) * NSLOT + c) * 2 + (s & 1)] = v;
    }
    __syncthreads();

    linear2<13, 64>(w0, Abuf, Bbuf, tid);  __syncthreads();
    adj2(aw0, b0, Bbuf, Abuf, tid, true);  __syncthreads();
    linear2<64, 64>(w1, Abuf, Bbuf, tid);  __syncthreads();
    adj2(aw1, b1, Bbuf, Abuf, tid, true);  __syncthreads();
    linear2<64, 64>(w2, Abuf, Bbuf, tid);  __syncthreads();
    adj2(aw2, b2, Bbuf, Abuf, tid, true);  __syncthreads();
    linear2<64, 68>(g_w3p, Abuf, Bbuf, tid); __syncthreads();
    adj_final2(aw3, b3, Bbuf, out + (size_t)B0 * (NJ * 65), nvalid, tid);
}

extern "C" void kernel_launch(void* const* d_in, const int* in_sizes, int n_in,
                              void* d_out, int out_size) {
    // Identify inputs by element count (robust to metadata ordering).
    const float* x = nullptr;
    const float* w[4] = {nullptr, nullptr, nullptr, nullptr};
    const float* aw[4] = {nullptr, nullptr, nullptr, nullptr};
    const float* b[4] = {nullptr, nullptr, nullptr, nullptr};
    int iw12 = 1, iaw = 0, ib = 0;
    int Btot = 0;
    for (int i = 0; i < n_in; i++) {
        int sz = in_sizes[i];
        const float* p = (const float*)d_in[i];
        if (sz == 24 * 13 * 64) {
            w[0] = p;
        } else if (sz == 24 * 64 * 64) {
            if (iw12 < 3) w[iw12++] = p;
        } else if (sz == 24 * 64 * 65) {
            w[3] = p;
        } else if (sz == 24 * 24) {
            if (iaw < 4) aw[iaw++] = p;
        } else if (sz == 64) {
            if (ib < 3) b[ib++] = p;
        } else if (sz == 65) {
            b[3] = p;
        } else {
            x = p;
            Btot = sz / (NJ * 13);
        }
    }

    (void)cudaFuncSetAttribute(gnn_fused, cudaFuncAttributeMaxDynamicSharedMemorySize, SMEM_BYTES);

    prep_w3_kernel<<<(NJ * 64 * 68 + 255) / 256, 256>>>(w[3]);

    int blocks = (Btot + TB - 1) / TB;
    gnn_fused<<<blocks, NTHREADS, SMEM_BYTES>>>(
        x, w[0], w[1], w[2],
        aw[0], aw[1], aw[2], aw[3],
        b[0], b[1], b[2], b[3],
        (float*)d_out, Btot);
}

// round 5
// speedup vs baseline: 1.0658x; 1.0186x over previous
#include <cuda_runtime.h>

#define NJ 24
#define TB 16
#define NP 8                        // sample pairs per block (f32x2 packing)
#define NPH 4                       // pairs handled per thread (NP / 2 phases)
#define NSLOT 68
#define PSTR (NJ * NSLOT + 2)       // 1634 float2 per pair-slot (pad: ph-groups on different banks)
#define NTHREADS 768
#define SMEM_BYTES (2 * NP * PSTR * 8)   // 209152 B (two float2 buffers)

typedef unsigned long long ull;

// ---- f32x2 packed helpers (ptxas never emits FFMA2 from C++) ----
__device__ __forceinline__ ull pack2(float lo, float hi) {
    ull r; asm("mov.b64 %0, {%1, %2};" : "=l"(r) : "f"(lo), "f"(hi)); return r;
}
__device__ __forceinline__ ull fma2(ull a, ull b, ull c) {
    ull d; asm("fma.rn.f32x2 %0, %1, %2, %3;" : "=l"(d) : "l"(a), "l"(b), "l"(c)); return d;
}
__device__ __forceinline__ ull add2(ull a, ull b) {
    ull d; asm("add.rn.f32x2 %0, %1, %2;" : "=l"(d) : "l"(a), "l"(b)); return d;
}
__device__ __forceinline__ ull relu2(ull v) {
    float lo, hi;
    asm("mov.b64 {%0, %1}, %2;" : "=f"(lo), "=f"(hi) : "l"(v));
    return pack2(fmaxf(lo, 0.f), fmaxf(hi, 0.f));
}

// Kinematic-tree adjacency (self + parent + children), CSR. 70 nonzeros.
__constant__ int cPTR[NJ + 1] = {0,4,7,10,13,16,19,22,25,28,33,35,37,40,43,46,48,51,54,57,60,63,66,68,70};
__constant__ int cCOL[70] = {
    0,1,2,3,  1,0,4,  2,0,5,  3,0,6,  4,1,7,  5,2,8,  6,3,9,  7,4,10,
    8,5,11,  9,6,12,13,14,  10,7,  11,8,  12,9,15,  13,9,16,  14,9,17,
    15,12,  16,13,18,  17,14,19,  18,16,20,  19,17,21,  20,18,22,
    21,19,23,  22,20,  23,21};

// w3 repacked [24][64][68] (cols 65..67 zero) so rows are 16B-aligned for float4 loads.
__device__ float g_w3p[NJ * 64 * 68];

__global__ void prep_w3_kernel(const float* __restrict__ w3) {
    int idx = blockIdx.x * blockDim.x + threadIdx.x;
    if (idx < NJ * 64 * 68) {
        int j = idx % 68;
        int nl = idx / 68;
        g_w3p[idx] = (j < 65) ? w3[nl * 65 + j] : 0.0f;
    }
}

// Per-node linear on pair-packed activations.
// Work item = (n, jv, ph): joint n, 4 output cols jv*4.., pairs [ph*NPH, ph*NPH+NPH).
// Adjacent threads (2jv, 2jv+1) share the same weight vector -> LDG dedup in L1tex.
template <int DIN, int DOUT>
__device__ __forceinline__ void linear2(const float* __restrict__ W,
                                        const float2* __restrict__ A,
                                        float2* __restrict__ Bf, int tid) {
    constexpr int JV = DOUT / 4;
    for (int t = tid; t < NJ * JV * 2; t += NTHREADS) {
        int n = t / (JV * 2);
        int q = t - n * (JV * 2);
        int jv = q >> 1;
        int ph = q & 1;
        const float* wp = W + (n * DIN) * DOUT + jv * 4;
        const float2* ap = A + n * NSLOT + ph * (NPH * PSTR);
        ull acc[NPH][4];
#pragma unroll
        for (int p = 0; p < NPH; p++) {
            acc[p][0] = 0ull; acc[p][1] = 0ull; acc[p][2] = 0ull; acc[p][3] = 0ull;
        }
#pragma unroll 4
        for (int l = 0; l < DIN; l++) {
            float4 wv = *reinterpret_cast<const float4*>(wp + l * DOUT);
            ull wx = pack2(wv.x, wv.x), wy = pack2(wv.y, wv.y);
            ull wz = pack2(wv.z, wv.z), ww = pack2(wv.w, wv.w);
#pragma unroll
            for (int p = 0; p < NPH; p++) {
                ull a2 = *reinterpret_cast<const ull*>(ap + p * PSTR + l);  // LDS.64, 2-way bcast
                acc[p][0] = fma2(a2, wx, acc[p][0]);
                acc[p][1] = fma2(a2, wy, acc[p][1]);
                acc[p][2] = fma2(a2, wz, acc[p][2]);
                acc[p][3] = fma2(a2, ww, acc[p][3]);
            }
        }
        float2* op = Bf + n * NSLOT + jv * 4 + ph * (NPH * PSTR);
#pragma unroll
        for (int p = 0; p < NPH; p++) {
            ulonglong2 v0; v0.x = acc[p][0]; v0.y = acc[p][1];
            ulonglong2 v1; v1.x = acc[p][2]; v1.y = acc[p][3];
            *reinterpret_cast<ulonglong2*>(op + p * PSTR)     = v0;  // STS.128
            *reinterpret_cast<ulonglong2*>(op + p * PSTR + 2) = v1;
        }
    }
}

// Sparse adjacency + bias (+relu) on pair-packed data. Work item = (n, jv, ph).
__device__ __forceinline__ void adj2(const float* __restrict__ aw,
                                     const float* __restrict__ bias,
                                     const float2* __restrict__ Bf,
                                     float2* __restrict__ Aout,
                                     int tid, bool relu) {
    for (int t = tid; t < NJ * 32; t += NTHREADS) {
        int n = t >> 5;
        int q = t & 31;
        int jv = q >> 1;
        int ph = q & 1;
        int pofs = ph * (NPH * PSTR);
        float4 bbv = *reinterpret_cast<const float4*>(bias + jv * 4);
        ull acc[NPH][4];
#pragma unroll
        for (int p = 0; p < NPH; p++) {
            acc[p][0] = 0ull; acc[p][1] = 0ull; acc[p][2] = 0ull; acc[p][3] = 0ull;
        }
        int e1 = cPTR[n + 1];
        for (int e = cPTR[n]; e < e1; e++) {
            int m = cCOL[e];
            float v = aw[n * NJ + m];
            ull v2 = pack2(v, v);
            const float2* bp = Bf + m * NSLOT + jv * 4 + pofs;
#pragma unroll
            for (int p = 0; p < NPH; p++) {
                ulonglong2 h0 = *reinterpret_cast<const ulonglong2*>(bp + p * PSTR);      // LDS.128
                ulonglong2 h1 = *reinterpret_cast<const ulonglong2*>(bp + p * PSTR + 2);
                acc[p][0] = fma2(v2, h0.x, acc[p][0]);
                acc[p][1] = fma2(v2, h0.y, acc[p][1]);
                acc[p][2] = fma2(v2, h1.x, acc[p][2]);
                acc[p][3] = fma2(v2, h1.y, acc[p][3]);
            }
        }
        ull bb0 = pack2(bbv.x, bbv.x), bb1 = pack2(bbv.y, bbv.y);
        ull bb2 = pack2(bbv.z, bbv.z), bb3 = pack2(bbv.w, bbv.w);
        float2* op = Aout + n * NSLOT + jv * 4 + pofs;
#pragma unroll
        for (int p = 0; p < NPH; p++) {
            ull r0 = add2(acc[p][0], bb0);
            ull r1 = add2(acc[p][1], bb1);
            ull r2 = add2(acc[p][2], bb2);
            ull r3 = add2(acc[p][3], bb3);
            if (relu) { r0 = relu2(r0); r1 = relu2(r1); r2 = relu2(r2); r3 = relu2(r3); }
            ulonglong2 v0; v0.x = r0; v0.y = r1;
            ulonglong2 v1; v1.x = r2; v1.y = r3;
            *reinterpret_cast<ulonglong2*>(op + p * PSTR)     = v0;
            *reinterpret_cast<ulonglong2*>(op + p * PSTR + 2) = v1;
        }
    }
}

// Final adjacency + bias, unpack pairs and write straight to gmem (dout=65).
__device__ __forceinline__ void adj_final2(const float* __restrict__ aw,
                                           const float* __restrict__ bias,
                                           const float2* __restrict__ Bf,
                                           float* __restrict__ outp,
                                           int nvalid, int tid) {
    for (int t = tid; t < NJ * 65 * 2; t += NTHREADS) {
        int half = t / (NJ * 65);          // 0 or 1
        int r = t - half * (NJ * 65);
        int n = r / 65;
        int j = r - n * 65;
        int pofs = half * (NPH * PSTR);
        float bb = bias[j];
        float ax[NPH], ay[NPH];
#pragma unroll
        for (int p = 0; p < NPH; p++) { ax[p] = bb; ay[p] = bb; }
        int e1 = cPTR[n + 1];
        for (int e = cPTR[n]; e < e1; e++) {
            int m = cCOL[e];
            float v = aw[n * NJ + m];
            const float2* bp = Bf + m * NSLOT + j + pofs;
#pragma unroll
            for (int p = 0; p < NPH; p++) {
                float2 h = bp[p * PSTR];
                ax[p] = fmaf(v, h.x, ax[p]);
                ay[p] = fmaf(v, h.y, ay[p]);
            }
        }
#pragma unroll
        for (int p = 0; p < NPH; p++) {
            int s0 = 2 * (half * NPH + p), s1 = s0 + 1;
            if (s0 < nvalid) outp[(size_t)s0 * (NJ * 65) + n * 65 + j] = ax[p];
            if (s1 < nvalid) outp[(size_t)s1 * (NJ * 65) + n * 65 + j] = ay[p];
        }
    }
}

__global__ __launch_bounds__(NTHREADS, 1)
void gnn_fused(const float* __restrict__ x,
               const float* __restrict__ w0, const float* __restrict__ w1,
               const float* __restrict__ w2,
               const float* __restrict__ aw0, const float* __restrict__ aw1,
               const float* __restrict__ aw2, const float* __restrict__ aw3,
               const float* __restrict__ b0, const float* __restrict__ b1,
               const float* __restrict__ b2, const float* __restrict__ b3,
               float* __restrict__ out, int Btot) {
    extern __shared__ float2 smem[];
    float2* Abuf = smem;
    float2* Bbuf = smem + NP * PSTR;
    int tid = threadIdx.x;
    int B0 = blockIdx.x * TB;
    int nvalid = Btot - B0;
    if (nvalid > TB) nvalid = TB;

    // Load x tile into pair-interleaved layout, apply root mask (joint 0 -> 0).
    float* dst = reinterpret_cast<float*>(Abuf);
    for (int i = tid; i < TB * NJ * 13; i += NTHREADS) {
        int s = i / (NJ * 13);
        int r = i - s * (NJ * 13);
        int n = r / 13;
        int c = r - n * 13;
        float v = 0.0f;
        if (s < nvalid && n != 0) v = x[(size_t)B0 * (NJ * 13) + i];
        dst[((s >> 1) * PSTR + n * NSLOT + c) * 2 + (s & 1)] = v;
    }
    __syncthreads();

    linear2<13, 64>(w0, Abuf, Bbuf, tid);  __syncthreads();
    adj2(aw0, b0, Bbuf, Abuf, tid, true);  __syncthreads();
    linear2<64, 64>(w1, Abuf, Bbuf, tid);  __syncthreads();
    adj2(aw1, b1, Bbuf, Abuf, tid, true);  __syncthreads();
    linear2<64, 64>(w2, Abuf, Bbuf, tid);  __syncthreads();
    adj2(aw2, b2, Bbuf, Abuf, tid, true);  __syncthreads();
    linear2<64, 68>(g_w3p, Abuf, Bbuf, tid); __syncthreads();
    adj_final2(aw3, b3, Bbuf, out + (size_t)B0 * (NJ * 65), nvalid, tid);
}

extern "C" void kernel_launch(void* const* d_in, const int* in_sizes, int n_in,
                              void* d_out, int out_size) {
    // Identify inputs by element count (robust to metadata ordering).
    const float* x = nullptr;
    const float* w[4] = {nullptr, nullptr, nullptr, nullptr};
    const float* aw[4] = {nullptr, nullptr, nullptr, nullptr};
    const float* b[4] = {nullptr, nullptr, nullptr, nullptr};
    int iw12 = 1, iaw = 0, ib = 0;
    int Btot = 0;
    for (int i = 0; i < n_in; i++) {
        int sz = in_sizes[i];
        const float* p = (const float*)d_in[i];
        if (sz == 24 * 13 * 64) {
            w[0] = p;
        } else if (sz == 24 * 64 * 64) {
            if (iw12 < 3) w[iw12++] = p;
        } else if (sz == 24 * 64 * 65) {
            w[3] = p;
        } else if (sz == 24 * 24) {
            if (iaw < 4) aw[iaw++] = p;
        } else if (sz == 64) {
            if (ib < 3) b[ib++] = p;
        } else if (sz == 65) {
            b[3] = p;
        } else {
            x = p;
            Btot = sz / (NJ * 13);
        }
    }

    (void)cudaFuncSetAttribute(gnn_fused, cudaFuncAttributeMaxDynamicSharedMemorySize, SMEM_BYTES);

    prep_w3_kernel<<<(NJ * 64 * 68 + 255) / 256, 256>>>(w[3]);

    int blocks = (Btot + TB - 1) / TB;
    gnn_fused<<<blocks, NTHREADS, SMEM_BYTES>>>(
        x, w[0], w[1], w[2],
        aw[0], aw[1], aw[2], aw[3],
        b[0], b[1], b[2], b[3],
        (float*)d_out, Btot);
}